// round 12
// baseline (speedup 1.0000x reference)
#include <cuda_runtime.h>
#include <cuda_fp16.h>
#include <cstdint>

#define B_  8
#define E_  512
#define L_  8192
#define KS  5
#define LC  8188
#define LD_ 4096

#define BM 128
#define BN 256
#define KC 64
#define NST 8                      // K stages (512/64)
#define NTHREADS 256
#define T_PAD 8448                 // padded t length per (b,stage) region

#define A_STG 81920                // 5 tap * 128 m * 128B
#define B_STG 33280                // 260 t rows * 128B
#define STAGE 115200
#define HDR   1024
#define SMEM_TOT (HDR + 2*STAGE)   // 231424 <= 232448

// ---------------- scratch ----------------------------------------------------
// x, stage-tiled + SW128 pre-swizzled: [b][stage][t(T_PAD)][64 e * 2B]
__device__ unsigned char g_xS[(size_t)B_*NST*T_PAD*128];
// w, stage-tiled + SW128 pre-swizzled: [oblk(4)][stage(8)][tap(5)][m(128)][64 i * 2B]
__device__ unsigned char g_wS[(size_t)4*NST*KS*128*128];
__device__ __half g_y[(size_t)B_*E_*LC];
__device__ float  g_s[(size_t)B_*L_];

// ---------------- asm helpers ------------------------------------------------
__device__ __forceinline__ uint32_t smem_u32(const void* p) {
    uint32_t a;
    asm("{ .reg .u64 t; cvta.to.shared.u64 t, %1; cvt.u32.u64 %0, t; }" : "=r"(a) : "l"(p));
    return a;
}
#define MBAR_INIT(a, n) asm volatile("mbarrier.init.shared.b64 [%0], %1;" :: "r"(a), "r"(n) : "memory")
#define MBAR_TX(a, n)   asm volatile("mbarrier.arrive.expect_tx.shared.b64 _, [%0], %1;" :: "r"(a), "r"(n) : "memory")
#define MBAR_WAIT(a, ph) do {                                                        \
    uint32_t _m = (a), _p = (ph), _d;                                                \
    asm volatile("{\n\t.reg .pred p;\n\t"                                            \
        "mbarrier.try_wait.parity.acquire.cta.shared::cta.b64 p, [%1], %2;\n\t"      \
        "selp.b32 %0, 1, 0, p;\n\t}" : "=r"(_d) : "r"(_m), "r"(_p) : "memory");      \
    if (!_d) {                                                                       \
        asm volatile("{\n\t.reg .pred P1;\n\t"                                       \
            "W%=:\n\t"                                                               \
            "mbarrier.try_wait.parity.acquire.cta.shared::cta.b64 P1, [%0], %1, 0x989680;\n\t" \
            "@P1 bra.uni D%=;\n\t"                                                   \
            "bra.uni W%=;\n\t"                                                       \
            "D%=:\n\t}" :: "r"(_m), "r"(_p) : "memory");                             \
    }                                                                                \
} while (0)
__device__ __forceinline__ void bulk_cp(uint32_t dst, const void* src, uint32_t bytes, uint32_t mbar) {
    asm volatile("cp.async.bulk.shared::cluster.global.mbarrier::complete_tx::bytes "
                 "[%0], [%1], %2, [%3];"
                 :: "r"(dst), "l"(src), "r"(bytes), "r"(mbar) : "memory");
}
#define LDSM4(r0, r1, r2, r3, addr) \
    asm volatile("ldmatrix.sync.aligned.m8n8.x4.shared.b16 {%0,%1,%2,%3}, [%4];" \
        : "=r"(r0), "=r"(r1), "=r"(r2), "=r"(r3) : "r"(addr))

__device__ __forceinline__ void mma_f16(float c[4], const uint32_t a[4],
                                        uint32_t b0, uint32_t b1) {
    asm volatile(
        "mma.sync.aligned.m16n8k16.row.col.f32.f16.f16.f32 "
        "{%0,%1,%2,%3}, {%4,%5,%6,%7}, {%8,%9}, {%0,%1,%2,%3};\n"
        : "+f"(c[0]), "+f"(c[1]), "+f"(c[2]), "+f"(c[3])
        : "r"(a[0]), "r"(a[1]), "r"(a[2]), "r"(a[3]), "r"(b0), "r"(b1));
}

__device__ __forceinline__ uint32_t sw128(uint32_t a) { return a ^ ((a >> 3) & 0x70); }

// ---------------- setup kernels ----------------------------------------------
// 64e x 32t tile: transpose in smem, write full swizzled 128B rows as uint4.
// blocks with blockIdx.y==0 also zero the score buffer for their t-span.
__global__ void cvt_x(const float* __restrict__ x) {
    __shared__ float tile[64][33];
    const int b = blockIdx.z, e0 = blockIdx.y * 64, t0 = blockIdx.x * 32;
    const int tx = threadIdx.x & 31, ty = threadIdx.x >> 5;   // ty 0..7
    if (blockIdx.y == 0 && threadIdx.x < 32)
        g_s[(size_t)b*L_ + t0 + threadIdx.x] = 0.f;
    #pragma unroll
    for (int r = 0; r < 8; r++)
        tile[ty + 8*r][tx] = x[((size_t)b*E_ + e0 + ty + 8*r)*L_ + t0 + tx];
    __syncthreads();
    const int st = e0 >> 6;
    const int tl = threadIdx.x >> 3, c = threadIdx.x & 7;     // t-local, 16B chunk
    const int t = t0 + tl;
    __half hv[8];
    #pragma unroll
    for (int j = 0; j < 8; j++) hv[j] = __float2half(tile[c*8 + j][tl]);
    size_t base = ((size_t)(b*NST + st)*T_PAD + (t & ~7)) * 128;
    uint32_t off = sw128((uint32_t)((t & 7)*128 + c*16));
    *reinterpret_cast<uint4*>(g_xS + base + off) = *reinterpret_cast<const uint4*>(hv);
}

__global__ void cvt_w(const float* __restrict__ w) {
    int i = blockIdx.x * 256 + threadIdx.x;
    if (i >= E_*E_*KS) return;
    int k  = i % KS;
    int r  = i / KS;
    int ic = r % E_, o = r / E_;
    __half h = __float2half(w[i]);
    int ob = o >> 7, m = o & 127, st = ic >> 6, iL = ic & 63;
    size_t atom = ((size_t)((ob*NST + st)*KS + k)*16 + (m >> 3)) * 1024;
    uint32_t off = sw128((uint32_t)((m & 7)*128 + iL*2));
    *reinterpret_cast<__half*>(g_wS + atom + off) = h;
}

// ---------------- main GEMM (conv as 5 shifted GEMMs) + fused score ----------
__global__ void __launch_bounds__(NTHREADS, 1) gemm_conv(
    const float* __restrict__ conv_b, const float* __restrict__ score_w)
{
    extern __shared__ char smem[];
    const uint32_t su = smem_u32(smem);
    const int tid = threadIdx.x, warp = tid >> 5, lane = tid & 31;
    const int b = blockIdx.z, ob = blockIdx.y, t0 = blockIdx.x * BN;
    const int o0 = ob * BM;
    const int wm = (warp >> 2) * 64, wn = (warp & 3) * 64;
    const uint32_t mb0 = su, mb1 = su + 8;       // full barriers, buf 0/1

    if (tid == 0) { MBAR_INIT(mb0, 1); MBAR_INIT(mb1, 1); }
    __syncthreads();

    auto issue = [&](int s) {
        uint32_t mb = (s & 1) ? mb1 : mb0;
        uint32_t dst = su + HDR + (uint32_t)(s & 1)*STAGE;
        MBAR_TX(mb, STAGE);
        bulk_cp(dst, g_wS + (size_t)(ob*NST + s)*A_STG, A_STG, mb);
        bulk_cp(dst + A_STG,
                g_xS + ((size_t)(b*NST + s)*T_PAD + t0)*128, B_STG, mb);
    };
    if (tid == 0) { issue(0); issue(1); }

    float acc[4][8][4];
    #pragma unroll
    for (int mf = 0; mf < 4; mf++)
        #pragma unroll
        for (int nf = 0; nf < 8; nf++)
            #pragma unroll
            for (int q = 0; q < 4; q++) acc[mf][nf][q] = 0.f;

    // per-lane fragment geometry
    const int mA   = wm + (lane & 15);                       // A row (per mf: +16*mf)
    const int mAq  = mA >> 3, mAr = (mA & 7);                // atom row / in-atom row
    const int aKh  = (lane >> 4) * 16;                       // A k-half byte
    const int rB0  = wn + (lane & 7) + ((lane >> 4) & 1)*8;  // B row (per nfp: +16*nfp)
    const int bKh  = ((lane >> 3) & 1) * 16;                 // B k-half byte

    for (int s = 0; s < NST; s++) {
        uint32_t mb = (s & 1) ? mb1 : mb0;
        MBAR_WAIT(mb, (s >> 1) & 1);

        const uint32_t Ab = su + HDR + (uint32_t)(s & 1)*STAGE;
        const uint32_t Bb = Ab + A_STG;

        #pragma unroll
        for (int tap = 0; tap < KS; tap++) {
            const int rt  = rB0 + tap;
            const uint32_t bRow = Bb + (uint32_t)((rt >> 3) * 1024 + (rt & 7) * 128);
            const uint32_t bXor = (uint32_t)((rt & 7) * 16);
            const uint32_t aTap = Ab + (uint32_t)(tap * 16384 + mAq * 1024 + mAr * 128);
            const uint32_t aXor = (uint32_t)(mAr * 16);
            #pragma unroll
            for (int kc = 0; kc < 4; kc++) {
                const uint32_t kbB = (uint32_t)(kc*32 + bKh) ^ bXor;
                const uint32_t kbA = (uint32_t)(kc*32 + aKh) ^ aXor;
                uint32_t bfr[4][4];
                #pragma unroll
                for (int nfp = 0; nfp < 4; nfp++)
                    LDSM4(bfr[nfp][0], bfr[nfp][1], bfr[nfp][2], bfr[nfp][3],
                          bRow + (uint32_t)(nfp * 2048) + kbB);
                uint32_t a[4][4];
                #pragma unroll
                for (int mf = 0; mf < 4; mf++)
                    LDSM4(a[mf][0], a[mf][1], a[mf][2], a[mf][3],
                          aTap + (uint32_t)(mf * 2048) + kbA);
                #pragma unroll
                for (int mf = 0; mf < 4; mf++)
                    #pragma unroll
                    for (int nf = 0; nf < 8; nf++) {
                        int nfp = nf >> 1, q = (nf & 1)*2;
                        mma_f16(acc[mf][nf], a[mf], bfr[nfp][q], bfr[nfp][q+1]);
                    }
            }
        }
        __syncthreads();
        if (tid == 0 && s + 2 < NST) issue(s + 2);
    }

    // ---- epilogue: bias, store y (fp16), fused score reduction (fp32) -------
    const int ar = lane >> 2, aq = (lane & 3)*2;
    float bvv[4][2], wsv[4][2];
    #pragma unroll
    for (int mf = 0; mf < 4; mf++) {
        int o = o0 + wm + mf*16 + ar;
        bvv[mf][0] = conv_b[o];     bvv[mf][1] = conv_b[o + 8];
        wsv[mf][0] = score_w[o];    wsv[mf][1] = score_w[o + 8];
    }
    #pragma unroll
    for (int mf = 0; mf < 4; mf++) {
        int o = o0 + wm + mf*16 + ar;
        #pragma unroll
        for (int nf = 0; nf < 8; nf++) {
            int t = t0 + wn + nf*8 + aq;
            if (t < LC) {   // t even, LC even => t+1 < LC too
                float y0 = acc[mf][nf][0] + bvv[mf][0];
                float y1 = acc[mf][nf][1] + bvv[mf][0];
                float y2 = acc[mf][nf][2] + bvv[mf][1];
                float y3 = acc[mf][nf][3] + bvv[mf][1];
                size_t r0 = ((size_t)(b*E_ + o))*LC + t;
                size_t r1 = r0 + (size_t)8*LC;
                *reinterpret_cast<__half2*>(&g_y[r0]) = __floats2half2_rn(y0, y1);
                *reinterpret_cast<__half2*>(&g_y[r1]) = __floats2half2_rn(y2, y3);
            }
        }
    }
    #pragma unroll
    for (int nf = 0; nf < 8; nf++) {
        float s0 = 0.f, s1 = 0.f;
        #pragma unroll
        for (int mf = 0; mf < 4; mf++) {
            s0 += wsv[mf][0]*(acc[mf][nf][0] + bvv[mf][0])
                + wsv[mf][1]*(acc[mf][nf][2] + bvv[mf][1]);
            s1 += wsv[mf][0]*(acc[mf][nf][1] + bvv[mf][0])
                + wsv[mf][1]*(acc[mf][nf][3] + bvv[mf][1]);
        }
        #pragma unroll
        for (int d = 4; d <= 16; d <<= 1) {
            s0 += __shfl_xor_sync(0xFFFFFFFFu, s0, d);
            s1 += __shfl_xor_sync(0xFFFFFFFFu, s1, d);
        }
        if (lane < 4) {
            int t = t0 + wn + nf*8 + aq;
            if (t < LC)     atomicAdd(&g_s[(size_t)b*L_ + t],     s0);
            if (t + 1 < LC) atomicAdd(&g_s[(size_t)b*L_ + t + 1], s1);
        }
    }
}

// ---------------- GBST combine + downsample ----------------------------------
// att computed once per block (2 syncs); channel loop is sync-free with
// direct guarded y loads (6-value register window per output pair).
__global__ void epilogue_kernel(float* __restrict__ out) {
    __shared__ float ss[520];
    __shared__ float att[3][512];
    const int tid = threadIdx.x;
    const int b  = blockIdx.y;
    const int t0 = blockIdx.x * 512;
    const int eg = blockIdx.z * 32;

    for (int j = tid; j < 516; j += 256) {
        int t = t0 - 2 + j;
        ss[j] = ((unsigned)t < (unsigned)L_) ? g_s[(size_t)b*L_ + t] : 0.f;
    }
    __syncthreads();
    for (int tl = tid; tl < 512; tl += 256) {
        int t = t0 + tl;
        float sc1 = ss[tl + 2];
        int b2 = (t & ~1) - t0;
        float sc2 = 0.5f * (ss[b2 + 2] + ss[b2 + 3]);
        int b3 = (t - (t % 3)) - t0;
        float sc3 = (1.f/3.f) * (ss[b3 + 2] + ss[b3 + 3] + ss[b3 + 4]);
        float m = fmaxf(sc1, fmaxf(sc2, sc3));
        float e1 = __expf(sc1 - m), e2 = __expf(sc2 - m), e3 = __expf(sc3 - m);
        float inv = 1.f / (e1 + e2 + e3);
        att[0][tl] = e1 * inv; att[1][tl] = e2 * inv; att[2][tl] = e3 * inv;
    }
    __syncthreads();

    const int td  = blockIdx.x * 256 + tid;   // output index
    const int T   = 2 * td;                   // global t of h=0
    const int tl0 = T - t0;                   // local t (even)
    const int r   = T % 3;
    const int r1  = (r == 2) ? 0 : r + 1;
    const float a10 = att[0][tl0],     a20 = att[1][tl0],     a30 = att[2][tl0];
    const float a11 = att[0][tl0 + 1], a21 = att[1][tl0 + 1], a31 = att[2][tl0 + 1];

    for (int ei = 0; ei < 32; ei++) {
        const __half* yrow = &g_y[(size_t)(b*E_ + eg + ei)*LC];
        float v[6];
        #pragma unroll
        for (int i = 0; i < 6; i++) {
            int ti = T - 2 + i;
            v[i] = ((unsigned)ti < (unsigned)LC) ? __half2float(yrow[ti]) : 0.f;
        }
        float p0 = v[0] + v[1] + v[2];
        float p1 = v[1] + v[2] + v[3];
        float p2 = v[2] + v[3] + v[4];
        float p3 = v[3] + v[4] + v[5];
        float s2  = 0.5f * (v[2] + v[3]);
        float s3a = (1.f/3.f) * (r == 0 ? p2 : (r == 1 ? p1 : p0));
        float s3b = (1.f/3.f) * (r1 == 0 ? p3 : (r1 == 1 ? p2 : p1));
        float z = a10*v[2] + a20*s2 + a30*s3a
                + a11*v[3] + a21*s2 + a31*s3b;
        out[(size_t)(b*E_ + eg + ei)*LD_ + td] = 0.5f * z;
    }
}

// ---------------- launch ------------------------------------------------------
extern "C" void kernel_launch(void* const* d_in, const int* in_sizes, int n_in,
                              void* d_out, int out_size) {
    const float* x       = (const float*)d_in[0];
    const float* conv_w  = (const float*)d_in[1];
    const float* conv_b  = (const float*)d_in[2];
    const float* score_w = (const float*)d_in[3];
    float* out = (float*)d_out;

    cvt_x<<<dim3(L_/32, E_/64, B_), 256>>>(x);
    cvt_w<<<(E_*E_*KS + 255)/256, 256>>>(conv_w);

    cudaFuncSetAttribute(gemm_conv, cudaFuncAttributeMaxDynamicSharedMemorySize, SMEM_TOT);
    gemm_conv<<<dim3(L_/BN, E_/BM, B_), NTHREADS, SMEM_TOT>>>(conv_b, score_w);

    epilogue_kernel<<<dim3(L_/512, B_, E_/32), 256>>>(out);
}

// round 13
// speedup vs baseline: 1.4423x; 1.4423x over previous
#include <cuda_runtime.h>
#include <cuda_fp16.h>
#include <cstdint>

#define B_  8
#define E_  512
#define L_  8192
#define KS  5
#define LC  8188
#define LD_ 4096

#define BM 128
#define BN 256
#define KC 64
#define NST 8                      // K stages (512/64)
#define NTHREADS 256
#define T_PAD 8448                 // padded t length per (b,stage) region

#define A_STG 81920                // 5 tap * 128 m * 128B
#define B_STG 33280                // 260 t rows * 128B
#define STAGE 115200
#define HDR   1024
#define SMEM_TOT (HDR + 2*STAGE)   // 231424 <= 232448

// ---------------- scratch ----------------------------------------------------
// x, stage-tiled + SW128 pre-swizzled: [b][stage][t(T_PAD)][64 e * 2B]
__device__ unsigned char g_xS[(size_t)B_*NST*T_PAD*128];
// w, stage-tiled + SW128 pre-swizzled: [oblk(4)][stage(8)][tap(5)][m(128)][64 i * 2B]
__device__ unsigned char g_wS[(size_t)4*NST*KS*128*128];
__device__ __half g_y[(size_t)B_*E_*LC];
__device__ float  g_s[(size_t)B_*L_];

// ---------------- asm helpers ------------------------------------------------
__device__ __forceinline__ uint32_t smem_u32(const void* p) {
    uint32_t a;
    asm("{ .reg .u64 t; cvta.to.shared.u64 t, %1; cvt.u32.u64 %0, t; }" : "=r"(a) : "l"(p));
    return a;
}
#define MBAR_INIT(a, n) asm volatile("mbarrier.init.shared.b64 [%0], %1;" :: "r"(a), "r"(n) : "memory")
#define MBAR_TX(a, n)   asm volatile("mbarrier.arrive.expect_tx.shared.b64 _, [%0], %1;" :: "r"(a), "r"(n) : "memory")
#define MBAR_WAIT(a, ph) do {                                                        \
    uint32_t _m = (a), _p = (ph), _d;                                                \
    asm volatile("{\n\t.reg .pred p;\n\t"                                            \
        "mbarrier.try_wait.parity.acquire.cta.shared::cta.b64 p, [%1], %2;\n\t"      \
        "selp.b32 %0, 1, 0, p;\n\t}" : "=r"(_d) : "r"(_m), "r"(_p) : "memory");      \
    if (!_d) {                                                                       \
        asm volatile("{\n\t.reg .pred P1;\n\t"                                       \
            "W%=:\n\t"                                                               \
            "mbarrier.try_wait.parity.acquire.cta.shared::cta.b64 P1, [%0], %1, 0x989680;\n\t" \
            "@P1 bra.uni D%=;\n\t"                                                   \
            "bra.uni W%=;\n\t"                                                       \
            "D%=:\n\t}" :: "r"(_m), "r"(_p) : "memory");                             \
    }                                                                                \
} while (0)
__device__ __forceinline__ void bulk_cp(uint32_t dst, const void* src, uint32_t bytes, uint32_t mbar) {
    asm volatile("cp.async.bulk.shared::cluster.global.mbarrier::complete_tx::bytes "
                 "[%0], [%1], %2, [%3];"
                 :: "r"(dst), "l"(src), "r"(bytes), "r"(mbar) : "memory");
}
#define LDSM4(r0, r1, r2, r3, addr) \
    asm volatile("ldmatrix.sync.aligned.m8n8.x4.shared.b16 {%0,%1,%2,%3}, [%4];" \
        : "=r"(r0), "=r"(r1), "=r"(r2), "=r"(r3) : "r"(addr))

__device__ __forceinline__ void mma_f16(float c[4], const uint32_t a[4],
                                        uint32_t b0, uint32_t b1) {
    asm volatile(
        "mma.sync.aligned.m16n8k16.row.col.f32.f16.f16.f32 "
        "{%0,%1,%2,%3}, {%4,%5,%6,%7}, {%8,%9}, {%0,%1,%2,%3};\n"
        : "+f"(c[0]), "+f"(c[1]), "+f"(c[2]), "+f"(c[3])
        : "r"(a[0]), "r"(a[1]), "r"(a[2]), "r"(a[3]), "r"(b0), "r"(b1));
}

__device__ __forceinline__ uint32_t sw128(uint32_t a) { return a ^ ((a >> 3) & 0x70); }

// ---------------- setup kernels ----------------------------------------------
__global__ void zero_s() {
    g_s[blockIdx.x * 1024 + threadIdx.x] = 0.f;
}

// 64e x 32t tile: transpose in smem, write full swizzled 128B rows as uint4
__global__ void cvt_x(const float* __restrict__ x) {
    __shared__ float tile[64][33];
    const int b = blockIdx.z, e0 = blockIdx.y * 64, t0 = blockIdx.x * 32;
    const int tx = threadIdx.x & 31, ty = threadIdx.x >> 5;   // ty 0..7
    #pragma unroll
    for (int r = 0; r < 8; r++)
        tile[ty + 8*r][tx] = x[((size_t)b*E_ + e0 + ty + 8*r)*L_ + t0 + tx];
    __syncthreads();
    const int st = e0 >> 6;
    const int tl = threadIdx.x >> 3, c = threadIdx.x & 7;     // t-local, 16B chunk
    const int t = t0 + tl;
    __half hv[8];
    #pragma unroll
    for (int j = 0; j < 8; j++) hv[j] = __float2half(tile[c*8 + j][tl]);
    size_t base = ((size_t)(b*NST + st)*T_PAD + (t & ~7)) * 128;
    uint32_t off = sw128((uint32_t)((t & 7)*128 + c*16));
    *reinterpret_cast<uint4*>(g_xS + base + off) = *reinterpret_cast<const uint4*>(hv);
}

__global__ void cvt_w(const float* __restrict__ w) {
    int i = blockIdx.x * 256 + threadIdx.x;
    if (i >= E_*E_*KS) return;
    int k  = i % KS;
    int r  = i / KS;
    int ic = r % E_, o = r / E_;
    __half h = __float2half(w[i]);
    int ob = o >> 7, m = o & 127, st = ic >> 6, iL = ic & 63;
    size_t atom = ((size_t)((ob*NST + st)*KS + k)*16 + (m >> 3)) * 1024;
    uint32_t off = sw128((uint32_t)((m & 7)*128 + iL*2));
    *reinterpret_cast<__half*>(g_wS + atom + off) = h;
}

// ---------------- main GEMM (conv as 5 shifted GEMMs) + fused score ----------
__global__ void __launch_bounds__(NTHREADS, 1) gemm_conv(
    const float* __restrict__ conv_b, const float* __restrict__ score_w)
{
    extern __shared__ char smem[];
    const uint32_t su = smem_u32(smem);
    const int tid = threadIdx.x, warp = tid >> 5, lane = tid & 31;
    const int b = blockIdx.z, ob = blockIdx.y, t0 = blockIdx.x * BN;
    const int o0 = ob * BM;
    const int wm = (warp >> 2) * 64, wn = (warp & 3) * 64;
    const uint32_t mb0 = su, mb1 = su + 8;       // full barriers, buf 0/1

    if (tid == 0) { MBAR_INIT(mb0, 1); MBAR_INIT(mb1, 1); }
    __syncthreads();

    auto issue = [&](int s) {
        uint32_t mb = (s & 1) ? mb1 : mb0;
        uint32_t dst = su + HDR + (uint32_t)(s & 1)*STAGE;
        MBAR_TX(mb, STAGE);
        bulk_cp(dst, g_wS + (size_t)(ob*NST + s)*A_STG, A_STG, mb);
        bulk_cp(dst + A_STG,
                g_xS + ((size_t)(b*NST + s)*T_PAD + t0)*128, B_STG, mb);
    };
    if (tid == 0) { issue(0); issue(1); }

    float acc[4][8][4];
    #pragma unroll
    for (int mf = 0; mf < 4; mf++)
        #pragma unroll
        for (int nf = 0; nf < 8; nf++)
            #pragma unroll
            for (int q = 0; q < 4; q++) acc[mf][nf][q] = 0.f;

    // per-lane fragment geometry
    const int mA   = wm + (lane & 15);                       // A row (per mf: +16*mf)
    const int mAq  = mA >> 3, mAr = (mA & 7);                // atom row / in-atom row
    const int aKh  = (lane >> 4) * 16;                       // A k-half byte
    const int rB0  = wn + (lane & 7) + ((lane >> 4) & 1)*8;  // B row (per nfp: +16*nfp)
    const int bKh  = ((lane >> 3) & 1) * 16;                 // B k-half byte

    for (int s = 0; s < NST; s++) {
        uint32_t mb = (s & 1) ? mb1 : mb0;
        MBAR_WAIT(mb, (s >> 1) & 1);

        const uint32_t Ab = su + HDR + (uint32_t)(s & 1)*STAGE;
        const uint32_t Bb = Ab + A_STG;

        #pragma unroll
        for (int tap = 0; tap < KS; tap++) {
            const int rt  = rB0 + tap;
            const uint32_t bRow = Bb + (uint32_t)((rt >> 3) * 1024 + (rt & 7) * 128);
            const uint32_t bXor = (uint32_t)((rt & 7) * 16);
            const uint32_t aTap = Ab + (uint32_t)(tap * 16384 + mAq * 1024 + mAr * 128);
            const uint32_t aXor = (uint32_t)(mAr * 16);
            #pragma unroll
            for (int kc = 0; kc < 4; kc++) {
                const uint32_t kbB = (uint32_t)(kc*32 + bKh) ^ bXor;
                const uint32_t kbA = (uint32_t)(kc*32 + aKh) ^ aXor;
                uint32_t bfr[4][4];
                #pragma unroll
                for (int nfp = 0; nfp < 4; nfp++)
                    LDSM4(bfr[nfp][0], bfr[nfp][1], bfr[nfp][2], bfr[nfp][3],
                          bRow + (uint32_t)(nfp * 2048) + kbB);
                uint32_t a[4][4];
                #pragma unroll
                for (int mf = 0; mf < 4; mf++)
                    LDSM4(a[mf][0], a[mf][1], a[mf][2], a[mf][3],
                          aTap + (uint32_t)(mf * 2048) + kbA);
                #pragma unroll
                for (int mf = 0; mf < 4; mf++)
                    #pragma unroll
                    for (int nf = 0; nf < 8; nf++) {
                        int nfp = nf >> 1, q = (nf & 1)*2;
                        mma_f16(acc[mf][nf], a[mf], bfr[nfp][q], bfr[nfp][q+1]);
                    }
            }
        }
        __syncthreads();
        if (tid == 0 && s + 2 < NST) issue(s + 2);
    }

    // ---- epilogue: bias, store y (fp16), fused score reduction (fp32) -------
    const int ar = lane >> 2, aq = (lane & 3)*2;
    float bvv[4][2], wsv[4][2];
    #pragma unroll
    for (int mf = 0; mf < 4; mf++) {
        int o = o0 + wm + mf*16 + ar;
        bvv[mf][0] = conv_b[o];     bvv[mf][1] = conv_b[o + 8];
        wsv[mf][0] = score_w[o];    wsv[mf][1] = score_w[o + 8];
    }
    #pragma unroll
    for (int mf = 0; mf < 4; mf++) {
        int o = o0 + wm + mf*16 + ar;
        #pragma unroll
        for (int nf = 0; nf < 8; nf++) {
            int t = t0 + wn + nf*8 + aq;
            if (t < LC) {   // t even, LC even => t+1 < LC too
                float y0 = acc[mf][nf][0] + bvv[mf][0];
                float y1 = acc[mf][nf][1] + bvv[mf][0];
                float y2 = acc[mf][nf][2] + bvv[mf][1];
                float y3 = acc[mf][nf][3] + bvv[mf][1];
                size_t r0 = ((size_t)(b*E_ + o))*LC + t;
                size_t r1 = r0 + (size_t)8*LC;
                *reinterpret_cast<__half2*>(&g_y[r0]) = __floats2half2_rn(y0, y1);
                *reinterpret_cast<__half2*>(&g_y[r1]) = __floats2half2_rn(y2, y3);
            }
        }
    }
    #pragma unroll
    for (int nf = 0; nf < 8; nf++) {
        float s0 = 0.f, s1 = 0.f;
        #pragma unroll
        for (int mf = 0; mf < 4; mf++) {
            s0 += wsv[mf][0]*(acc[mf][nf][0] + bvv[mf][0])
                + wsv[mf][1]*(acc[mf][nf][2] + bvv[mf][1]);
            s1 += wsv[mf][0]*(acc[mf][nf][1] + bvv[mf][0])
                + wsv[mf][1]*(acc[mf][nf][3] + bvv[mf][1]);
        }
        #pragma unroll
        for (int d = 4; d <= 16; d <<= 1) {
            s0 += __shfl_xor_sync(0xFFFFFFFFu, s0, d);
            s1 += __shfl_xor_sync(0xFFFFFFFFu, s1, d);
        }
        if (lane < 4) {
            int t = t0 + wn + nf*8 + aq;
            if (t < LC)     atomicAdd(&g_s[(size_t)b*L_ + t],     s0);
            if (t + 1 < LC) atomicAdd(&g_s[(size_t)b*L_ + t + 1], s1);
        }
    }
}

// ---------------- GBST combine + downsample ----------------------------------
// R11 structure (smem-staged, coalesced); 2 channels staged per iteration,
// 16 channels per block, half2-vectorized y loads.
#define EPB 16
__global__ void epilogue_kernel(float* __restrict__ out) {
    __shared__ float ss[520];
    __shared__ float att[3][512];
    __shared__ float ys[2][520];
    const int tid = threadIdx.x;
    const int b  = blockIdx.y;
    const int t0 = blockIdx.x * 512;
    const int eg = blockIdx.z * EPB;

    for (int j = tid; j < 516; j += 256) {
        int t = t0 - 2 + j;
        ss[j] = ((unsigned)t < (unsigned)L_) ? g_s[(size_t)b*L_ + t] : 0.f;
    }
    __syncthreads();
    for (int tl = tid; tl < 512; tl += 256) {
        int t = t0 + tl;
        float sc1 = ss[tl + 2];
        int b2 = (t & ~1) - t0;
        float sc2 = 0.5f * (ss[b2 + 2] + ss[b2 + 3]);
        int b3 = (t - (t % 3)) - t0;
        float sc3 = (1.f/3.f) * (ss[b3 + 2] + ss[b3 + 3] + ss[b3 + 4]);
        float m = fmaxf(sc1, fmaxf(sc2, sc3));
        float e1 = __expf(sc1 - m), e2 = __expf(sc2 - m), e3 = __expf(sc3 - m);
        float inv = 1.f / (e1 + e2 + e3);
        att[0][tl] = e1 * inv; att[1][tl] = e2 * inv; att[2][tl] = e3 * inv;
    }
    __syncthreads();

    const int td = blockIdx.x * 256 + tid;
    for (int ei = 0; ei < EPB; ei += 2) {
        // stage 2 channels, half2 loads (t base even => 4B aligned)
        for (int j = tid; j < 516; j += 256) {
            int ch = j >= 258;
            int jj = j - ch*258;
            int t  = t0 - 2 + 2*jj;
            const __half* yrow = &g_y[(size_t)(b*E_ + eg + ei + ch)*LC];
            float v0, v1;
            if (t >= 0 && t + 1 < LC) {
                __half2 h = *reinterpret_cast<const __half2*>(&yrow[t]);
                v0 = __low2float(h); v1 = __high2float(h);
            } else {
                v0 = ((unsigned)t       < (unsigned)LC) ? __half2float(yrow[t])     : 0.f;
                v1 = ((unsigned)(t + 1) < (unsigned)LC) ? __half2float(yrow[t + 1]) : 0.f;
            }
            ys[ch][2*jj] = v0;
            if (2*jj + 1 < 520) ys[ch][2*jj + 1] = v1;
        }
        __syncthreads();
        #pragma unroll
        for (int ch = 0; ch < 2; ch++) {
            float z = 0.f;
            #pragma unroll
            for (int h = 0; h < 2; h++) {
                int t  = 2*td + h;
                int tl = t - t0;
                float s1 = ys[ch][tl + 2];
                int b2 = (t & ~1) - t0;
                float s2 = 0.5f * (ys[ch][b2 + 2] + ys[ch][b2 + 3]);
                int b3 = (t - (t % 3)) - t0;
                float s3 = (1.f/3.f) * (ys[ch][b3 + 2] + ys[ch][b3 + 3] + ys[ch][b3 + 4]);
                z += att[0][tl]*s1 + att[1][tl]*s2 + att[2][tl]*s3;
            }
            out[(size_t)(b*E_ + eg + ei + ch)*LD_ + td] = 0.5f * z;
        }
        __syncthreads();
    }
}

// ---------------- launch ------------------------------------------------------
extern "C" void kernel_launch(void* const* d_in, const int* in_sizes, int n_in,
                              void* d_out, int out_size) {
    const float* x       = (const float*)d_in[0];
    const float* conv_w  = (const float*)d_in[1];
    const float* conv_b  = (const float*)d_in[2];
    const float* score_w = (const float*)d_in[3];
    float* out = (float*)d_out;

    zero_s<<<B_*L_/1024, 1024>>>();
    cvt_x<<<dim3(L_/32, E_/64, B_), 256>>>(x);
    cvt_w<<<(E_*E_*KS + 255)/256, 256>>>(conv_w);

    cudaFuncSetAttribute(gemm_conv, cudaFuncAttributeMaxDynamicSharedMemorySize, SMEM_TOT);
    gemm_conv<<<dim3(L_/BN, E_/BM, B_), NTHREADS, SMEM_TOT>>>(conv_b, score_w);

    epilogue_kernel<<<dim3(L_/512, B_, E_/EPB), 256>>>(out);
}

// round 14
// speedup vs baseline: 1.4616x; 1.0134x over previous
#include <cuda_runtime.h>
#include <cuda_fp16.h>
#include <cstdint>

#define B_  8
#define E_  512
#define L_  8192
#define KS  5
#define LC  8188
#define LD_ 4096

#define BM 128
#define BN 256
#define KC 64
#define NST 8                      // K stages (512/64)
#define NTHREADS 256
#define T_PAD 8448                 // padded t length per (b,stage) region

#define A_STG 81920                // 5 tap * 128 m * 128B
#define B_STG 33280                // 260 t rows * 128B
#define STAGE 115200
#define HDR   1024
#define SMEM_TOT (HDR + 2*STAGE)   // 231424 <= 232448

// ---------------- scratch ----------------------------------------------------
// x, stage-tiled + SW128 pre-swizzled: [b][stage][t(T_PAD)][64 e * 2B]
__device__ unsigned char g_xS[(size_t)B_*NST*T_PAD*128];
// w, stage-tiled + SW128 pre-swizzled: [oblk(4)][stage(8)][tap(5)][m(128)][64 i * 2B]
__device__ unsigned char g_wS[(size_t)4*NST*KS*128*128];
__device__ __half g_y[(size_t)B_*E_*LC];
__device__ float  g_s[(size_t)B_*L_];

// ---------------- asm helpers ------------------------------------------------
__device__ __forceinline__ uint32_t smem_u32(const void* p) {
    uint32_t a;
    asm("{ .reg .u64 t; cvta.to.shared.u64 t, %1; cvt.u32.u64 %0, t; }" : "=r"(a) : "l"(p));
    return a;
}
#define MBAR_INIT(a, n) asm volatile("mbarrier.init.shared.b64 [%0], %1;" :: "r"(a), "r"(n) : "memory")
#define MBAR_TX(a, n)   asm volatile("mbarrier.arrive.expect_tx.shared.b64 _, [%0], %1;" :: "r"(a), "r"(n) : "memory")
#define MBAR_WAIT(a, ph) do {                                                        \
    uint32_t _m = (a), _p = (ph), _d;                                                \
    asm volatile("{\n\t.reg .pred p;\n\t"                                            \
        "mbarrier.try_wait.parity.acquire.cta.shared::cta.b64 p, [%1], %2;\n\t"      \
        "selp.b32 %0, 1, 0, p;\n\t}" : "=r"(_d) : "r"(_m), "r"(_p) : "memory");      \
    if (!_d) {                                                                       \
        asm volatile("{\n\t.reg .pred P1;\n\t"                                       \
            "W%=:\n\t"                                                               \
            "mbarrier.try_wait.parity.acquire.cta.shared::cta.b64 P1, [%0], %1, 0x989680;\n\t" \
            "@P1 bra.uni D%=;\n\t"                                                   \
            "bra.uni W%=;\n\t"                                                       \
            "D%=:\n\t}" :: "r"(_m), "r"(_p) : "memory");                             \
    }                                                                                \
} while (0)
__device__ __forceinline__ void bulk_cp(uint32_t dst, const void* src, uint32_t bytes, uint32_t mbar) {
    asm volatile("cp.async.bulk.shared::cluster.global.mbarrier::complete_tx::bytes "
                 "[%0], [%1], %2, [%3];"
                 :: "r"(dst), "l"(src), "r"(bytes), "r"(mbar) : "memory");
}
#define LDSM4(r0, r1, r2, r3, addr) \
    asm volatile("ldmatrix.sync.aligned.m8n8.x4.shared.b16 {%0,%1,%2,%3}, [%4];" \
        : "=r"(r0), "=r"(r1), "=r"(r2), "=r"(r3) : "r"(addr))

__device__ __forceinline__ void mma_f16(float c[4], const uint32_t a[4],
                                        uint32_t b0, uint32_t b1) {
    asm volatile(
        "mma.sync.aligned.m16n8k16.row.col.f32.f16.f16.f32 "
        "{%0,%1,%2,%3}, {%4,%5,%6,%7}, {%8,%9}, {%0,%1,%2,%3};\n"
        : "+f"(c[0]), "+f"(c[1]), "+f"(c[2]), "+f"(c[3])
        : "r"(a[0]), "r"(a[1]), "r"(a[2]), "r"(a[3]), "r"(b0), "r"(b1));
}

__device__ __forceinline__ uint32_t sw128(uint32_t a) { return a ^ ((a >> 3) & 0x70); }

// ---------------- setup kernels ----------------------------------------------
// 64e x 64t tile: float4 loads, smem transpose, 2 swizzled uint4 stores/thread
__global__ void cvt_x(const float* __restrict__ x) {
    __shared__ float tile[64][65];
    const int b = blockIdx.z, e0 = blockIdx.y * 64, t0 = blockIdx.x * 64;
    #pragma unroll
    for (int it = 0; it < 4; it++) {
        int f = threadIdx.x + it*256;
        int e = f >> 4, c4 = (f & 15)*4;
        float4 v = *reinterpret_cast<const float4*>(
            &x[((size_t)b*E_ + e0 + e)*L_ + t0 + c4]);
        tile[e][c4+0] = v.x; tile[e][c4+1] = v.y;
        tile[e][c4+2] = v.z; tile[e][c4+3] = v.w;
    }
    __syncthreads();
    const int st = blockIdx.y;
    #pragma unroll
    for (int it = 0; it < 2; it++) {
        int q = threadIdx.x + it*256;
        int tl = q >> 3, c = q & 7;
        int t = t0 + tl;
        __half hv[8];
        #pragma unroll
        for (int j = 0; j < 8; j++) hv[j] = __float2half(tile[c*8 + j][tl]);
        size_t base = ((size_t)(b*NST + st)*T_PAD + (t & ~7)) * 128;
        uint32_t off = sw128((uint32_t)((t & 7)*128 + c*16));
        *reinterpret_cast<uint4*>(g_xS + base + off) = *reinterpret_cast<const uint4*>(hv);
    }
}

// also zeroes g_s (first 256 blocks), replacing the zero_s launch
__global__ void cvt_w(const float* __restrict__ w) {
    if (blockIdx.x < 256)
        g_s[blockIdx.x*256 + threadIdx.x] = 0.f;
    int i = blockIdx.x * 256 + threadIdx.x;
    if (i >= E_*E_*KS) return;
    int k  = i % KS;
    int r  = i / KS;
    int ic = r % E_, o = r / E_;
    __half h = __float2half(w[i]);
    int ob = o >> 7, m = o & 127, st = ic >> 6, iL = ic & 63;
    size_t atom = ((size_t)((ob*NST + st)*KS + k)*16 + (m >> 3)) * 1024;
    uint32_t off = sw128((uint32_t)((m & 7)*128 + iL*2));
    *reinterpret_cast<__half*>(g_wS + atom + off) = h;
}

// ---------------- main GEMM (conv as 5 shifted GEMMs) + fused score ----------
__global__ void __launch_bounds__(NTHREADS, 1) gemm_conv(
    const float* __restrict__ conv_b, const float* __restrict__ score_w)
{
    extern __shared__ char smem[];
    const uint32_t su = smem_u32(smem);
    const int tid = threadIdx.x, warp = tid >> 5, lane = tid & 31;
    const int b = blockIdx.z, ob = blockIdx.y, t0 = blockIdx.x * BN;
    const int o0 = ob * BM;
    const int wm = (warp >> 2) * 64, wn = (warp & 3) * 64;
    const uint32_t mb0 = su, mb1 = su + 8;       // full barriers, buf 0/1

    if (tid == 0) { MBAR_INIT(mb0, 1); MBAR_INIT(mb1, 1); }
    __syncthreads();

    auto issue = [&](int s) {
        uint32_t mb = (s & 1) ? mb1 : mb0;
        uint32_t dst = su + HDR + (uint32_t)(s & 1)*STAGE;
        MBAR_TX(mb, STAGE);
        bulk_cp(dst, g_wS + (size_t)(ob*NST + s)*A_STG, A_STG, mb);
        bulk_cp(dst + A_STG,
                g_xS + ((size_t)(b*NST + s)*T_PAD + t0)*128, B_STG, mb);
    };
    if (tid == 0) { issue(0); issue(1); }

    float acc[4][8][4];
    #pragma unroll
    for (int mf = 0; mf < 4; mf++)
        #pragma unroll
        for (int nf = 0; nf < 8; nf++)
            #pragma unroll
            for (int q = 0; q < 4; q++) acc[mf][nf][q] = 0.f;

    // per-lane fragment geometry
    const int mA   = wm + (lane & 15);                       // A row (per mf: +16*mf)
    const int mAq  = mA >> 3, mAr = (mA & 7);                // atom row / in-atom row
    const int aKh  = (lane >> 4) * 16;                       // A k-half byte
    const int rB0  = wn + (lane & 7) + ((lane >> 4) & 1)*8;  // B row (per nfp: +16*nfp)
    const int bKh  = ((lane >> 3) & 1) * 16;                 // B k-half byte

    for (int s = 0; s < NST; s++) {
        uint32_t mb = (s & 1) ? mb1 : mb0;
        MBAR_WAIT(mb, (s >> 1) & 1);

        const uint32_t Ab = su + HDR + (uint32_t)(s & 1)*STAGE;
        const uint32_t Bb = Ab + A_STG;

        #pragma unroll
        for (int tap = 0; tap < KS; tap++) {
            const int rt  = rB0 + tap;
            const uint32_t bRow = Bb + (uint32_t)((rt >> 3) * 1024 + (rt & 7) * 128);
            const uint32_t bXor = (uint32_t)((rt & 7) * 16);
            const uint32_t aTap = Ab + (uint32_t)(tap * 16384 + mAq * 1024 + mAr * 128);
            const uint32_t aXor = (uint32_t)(mAr * 16);
            #pragma unroll
            for (int kc = 0; kc < 4; kc++) {
                const uint32_t kbB = (uint32_t)(kc*32 + bKh) ^ bXor;
                const uint32_t kbA = (uint32_t)(kc*32 + aKh) ^ aXor;
                uint32_t bfr[4][4];
                #pragma unroll
                for (int nfp = 0; nfp < 4; nfp++)
                    LDSM4(bfr[nfp][0], bfr[nfp][1], bfr[nfp][2], bfr[nfp][3],
                          bRow + (uint32_t)(nfp * 2048) + kbB);
                uint32_t a[4][4];
                #pragma unroll
                for (int mf = 0; mf < 4; mf++)
                    LDSM4(a[mf][0], a[mf][1], a[mf][2], a[mf][3],
                          aTap + (uint32_t)(mf * 2048) + kbA);
                #pragma unroll
                for (int mf = 0; mf < 4; mf++)
                    #pragma unroll
                    for (int nf = 0; nf < 8; nf++) {
                        int nfp = nf >> 1, q = (nf & 1)*2;
                        mma_f16(acc[mf][nf], a[mf], bfr[nfp][q], bfr[nfp][q+1]);
                    }
            }
        }
        __syncthreads();
        if (tid == 0 && s + 2 < NST) issue(s + 2);
    }

    // ---- epilogue: bias, store y (fp16), fused score reduction (fp32) -------
    const int ar = lane >> 2, aq = (lane & 3)*2;
    float bvv[4][2], wsv[4][2];
    #pragma unroll
    for (int mf = 0; mf < 4; mf++) {
        int o = o0 + wm + mf*16 + ar;
        bvv[mf][0] = conv_b[o];     bvv[mf][1] = conv_b[o + 8];
        wsv[mf][0] = score_w[o];    wsv[mf][1] = score_w[o + 8];
    }
    #pragma unroll
    for (int mf = 0; mf < 4; mf++) {
        int o = o0 + wm + mf*16 + ar;
        #pragma unroll
        for (int nf = 0; nf < 8; nf++) {
            int t = t0 + wn + nf*8 + aq;
            if (t < LC) {   // t even, LC even => t+1 < LC too
                float y0 = acc[mf][nf][0] + bvv[mf][0];
                float y1 = acc[mf][nf][1] + bvv[mf][0];
                float y2 = acc[mf][nf][2] + bvv[mf][1];
                float y3 = acc[mf][nf][3] + bvv[mf][1];
                size_t r0 = ((size_t)(b*E_ + o))*LC + t;
                size_t r1 = r0 + (size_t)8*LC;
                *reinterpret_cast<__half2*>(&g_y[r0]) = __floats2half2_rn(y0, y1);
                *reinterpret_cast<__half2*>(&g_y[r1]) = __floats2half2_rn(y2, y3);
            }
        }
    }
    #pragma unroll
    for (int nf = 0; nf < 8; nf++) {
        float s0 = 0.f, s1 = 0.f;
        #pragma unroll
        for (int mf = 0; mf < 4; mf++) {
            s0 += wsv[mf][0]*(acc[mf][nf][0] + bvv[mf][0])
                + wsv[mf][1]*(acc[mf][nf][2] + bvv[mf][1]);
            s1 += wsv[mf][0]*(acc[mf][nf][1] + bvv[mf][0])
                + wsv[mf][1]*(acc[mf][nf][3] + bvv[mf][1]);
        }
        #pragma unroll
        for (int d = 4; d <= 16; d <<= 1) {
            s0 += __shfl_xor_sync(0xFFFFFFFFu, s0, d);
            s1 += __shfl_xor_sync(0xFFFFFFFFu, s1, d);
        }
        if (lane < 4) {
            int t = t0 + wn + nf*8 + aq;
            if (t < LC)     atomicAdd(&g_s[(size_t)b*L_ + t],     s0);
            if (t + 1 < LC) atomicAdd(&g_s[(size_t)b*L_ + t + 1], s1);
        }
    }
}

// ---------------- GBST combine + downsample ----------------------------------
// smem-staged, coalesced; 2 channels staged per iteration, 16 channels/block,
// half2-vectorized y loads. (R13-proven)
#define EPB 16
__global__ void epilogue_kernel(float* __restrict__ out) {
    __shared__ float ss[520];
    __shared__ float att[3][512];
    __shared__ float ys[2][520];
    const int tid = threadIdx.x;
    const int b  = blockIdx.y;
    const int t0 = blockIdx.x * 512;
    const int eg = blockIdx.z * EPB;

    for (int j = tid; j < 516; j += 256) {
        int t = t0 - 2 + j;
        ss[j] = ((unsigned)t < (unsigned)L_) ? g_s[(size_t)b*L_ + t] : 0.f;
    }
    __syncthreads();
    for (int tl = tid; tl < 512; tl += 256) {
        int t = t0 + tl;
        float sc1 = ss[tl + 2];
        int b2 = (t & ~1) - t0;
        float sc2 = 0.5f * (ss[b2 + 2] + ss[b2 + 3]);
        int b3 = (t - (t % 3)) - t0;
        float sc3 = (1.f/3.f) * (ss[b3 + 2] + ss[b3 + 3] + ss[b3 + 4]);
        float m = fmaxf(sc1, fmaxf(sc2, sc3));
        float e1 = __expf(sc1 - m), e2 = __expf(sc2 - m), e3 = __expf(sc3 - m);
        float inv = 1.f / (e1 + e2 + e3);
        att[0][tl] = e1 * inv; att[1][tl] = e2 * inv; att[2][tl] = e3 * inv;
    }
    __syncthreads();

    const int td = blockIdx.x * 256 + tid;
    for (int ei = 0; ei < EPB; ei += 2) {
        for (int j = tid; j < 516; j += 256) {
            int ch = j >= 258;
            int jj = j - ch*258;
            int t  = t0 - 2 + 2*jj;
            const __half* yrow = &g_y[(size_t)(b*E_ + eg + ei + ch)*LC];
            float v0, v1;
            if (t >= 0 && t + 1 < LC) {
                __half2 h = *reinterpret_cast<const __half2*>(&yrow[t]);
                v0 = __low2float(h); v1 = __high2float(h);
            } else {
                v0 = ((unsigned)t       < (unsigned)LC) ? __half2float(yrow[t])     : 0.f;
                v1 = ((unsigned)(t + 1) < (unsigned)LC) ? __half2float(yrow[t + 1]) : 0.f;
            }
            ys[ch][2*jj] = v0;
            if (2*jj + 1 < 520) ys[ch][2*jj + 1] = v1;
        }
        __syncthreads();
        #pragma unroll
        for (int ch = 0; ch < 2; ch++) {
            float z = 0.f;
            #pragma unroll
            for (int h = 0; h < 2; h++) {
                int t  = 2*td + h;
                int tl = t - t0;
                float s1 = ys[ch][tl + 2];
                int b2 = (t & ~1) - t0;
                float s2 = 0.5f * (ys[ch][b2 + 2] + ys[ch][b2 + 3]);
                int b3 = (t - (t % 3)) - t0;
                float s3 = (1.f/3.f) * (ys[ch][b3 + 2] + ys[ch][b3 + 3] + ys[ch][b3 + 4]);
                z += att[0][tl]*s1 + att[1][tl]*s2 + att[2][tl]*s3;
            }
            out[(size_t)(b*E_ + eg + ei + ch)*LD_ + td] = 0.5f * z;
        }
        __syncthreads();
    }
}

// ---------------- launch ------------------------------------------------------
extern "C" void kernel_launch(void* const* d_in, const int* in_sizes, int n_in,
                              void* d_out, int out_size) {
    const float* x       = (const float*)d_in[0];
    const float* conv_w  = (const float*)d_in[1];
    const float* conv_b  = (const float*)d_in[2];
    const float* score_w = (const float*)d_in[3];
    float* out = (float*)d_out;

    cvt_x<<<dim3(L_/64, E_/64, B_), 256>>>(x);
    cvt_w<<<(E_*E_*KS + 255)/256, 256>>>(conv_w);

    cudaFuncSetAttribute(gemm_conv, cudaFuncAttributeMaxDynamicSharedMemorySize, SMEM_TOT);
    gemm_conv<<<dim3(L_/BN, E_/BM, B_), NTHREADS, SMEM_TOT>>>(conv_b, score_w);

    epilogue_kernel<<<dim3(L_/512, B_, E_/EPB), 256>>>(out);
}

// round 15
// speedup vs baseline: 1.5382x; 1.0524x over previous
#include <cuda_runtime.h>
#include <cuda_fp16.h>
#include <cstdint>

#define B_  8
#define E_  512
#define L_  8192
#define KS  5
#define LC  8188
#define LCP 8192                   // padded y row stride (16B-aligned rows)
#define LD_ 4096

#define BM 128
#define BN 256
#define KC 64
#define NST 8                      // K stages (512/64)
#define NTHREADS 256
#define T_PAD 8448                 // padded t length per (b,stage) region

#define A_STG 81920                // 5 tap * 128 m * 128B
#define B_STG 33280                // 260 t rows * 128B
#define STAGE 115200
#define HDR   1024
#define SMEM_TOT (HDR + 2*STAGE)   // 231424 <= 232448

// ---------------- scratch ----------------------------------------------------
// x, stage-tiled + SW128 pre-swizzled: [b][stage][t(T_PAD)][64 e * 2B]
__device__ unsigned char g_xS[(size_t)B_*NST*T_PAD*128];
// w, stage-tiled + SW128 pre-swizzled: [oblk(4)][stage(8)][tap(5)][m(128)][64 i * 2B]
__device__ unsigned char g_wS[(size_t)4*NST*KS*128*128];
__device__ __half g_y[(size_t)B_*E_*LCP];
__device__ float  g_s[(size_t)B_*L_];

// ---------------- asm helpers ------------------------------------------------
__device__ __forceinline__ uint32_t smem_u32(const void* p) {
    uint32_t a;
    asm("{ .reg .u64 t; cvta.to.shared.u64 t, %1; cvt.u32.u64 %0, t; }" : "=r"(a) : "l"(p));
    return a;
}
#define MBAR_INIT(a, n) asm volatile("mbarrier.init.shared.b64 [%0], %1;" :: "r"(a), "r"(n) : "memory")
#define MBAR_TX(a, n)   asm volatile("mbarrier.arrive.expect_tx.shared.b64 _, [%0], %1;" :: "r"(a), "r"(n) : "memory")
#define MBAR_WAIT(a, ph) do {                                                        \
    uint32_t _m = (a), _p = (ph), _d;                                                \
    asm volatile("{\n\t.reg .pred p;\n\t"                                            \
        "mbarrier.try_wait.parity.acquire.cta.shared::cta.b64 p, [%1], %2;\n\t"      \
        "selp.b32 %0, 1, 0, p;\n\t}" : "=r"(_d) : "r"(_m), "r"(_p) : "memory");      \
    if (!_d) {                                                                       \
        asm volatile("{\n\t.reg .pred P1;\n\t"                                       \
            "W%=:\n\t"                                                               \
            "mbarrier.try_wait.parity.acquire.cta.shared::cta.b64 P1, [%0], %1, 0x989680;\n\t" \
            "@P1 bra.uni D%=;\n\t"                                                   \
            "bra.uni W%=;\n\t"                                                       \
            "D%=:\n\t}" :: "r"(_m), "r"(_p) : "memory");                             \
    }                                                                                \
} while (0)
__device__ __forceinline__ void bulk_cp(uint32_t dst, const void* src, uint32_t bytes, uint32_t mbar) {
    asm volatile("cp.async.bulk.shared::cluster.global.mbarrier::complete_tx::bytes "
                 "[%0], [%1], %2, [%3];"
                 :: "r"(dst), "l"(src), "r"(bytes), "r"(mbar) : "memory");
}
#define LDSM4(r0, r1, r2, r3, addr) \
    asm volatile("ldmatrix.sync.aligned.m8n8.x4.shared.b16 {%0,%1,%2,%3}, [%4];" \
        : "=r"(r0), "=r"(r1), "=r"(r2), "=r"(r3) : "r"(addr))

__device__ __forceinline__ void mma_f16(float c[4], const uint32_t a[4],
                                        uint32_t b0, uint32_t b1) {
    asm volatile(
        "mma.sync.aligned.m16n8k16.row.col.f32.f16.f16.f32 "
        "{%0,%1,%2,%3}, {%4,%5,%6,%7}, {%8,%9}, {%0,%1,%2,%3};\n"
        : "+f"(c[0]), "+f"(c[1]), "+f"(c[2]), "+f"(c[3])
        : "r"(a[0]), "r"(a[1]), "r"(a[2]), "r"(a[3]), "r"(b0), "r"(b1));
}

__device__ __forceinline__ uint32_t sw128(uint32_t a) { return a ^ ((a >> 3) & 0x70); }

// ---------------- setup kernels ----------------------------------------------
// 64e x 64t tile: float4 loads, smem transpose, 2 swizzled uint4 stores/thread
__global__ void cvt_x(const float* __restrict__ x) {
    __shared__ float tile[64][65];
    const int b = blockIdx.z, e0 = blockIdx.y * 64, t0 = blockIdx.x * 64;
    #pragma unroll
    for (int it = 0; it < 4; it++) {
        int f = threadIdx.x + it*256;
        int e = f >> 4, c4 = (f & 15)*4;
        float4 v = *reinterpret_cast<const float4*>(
            &x[((size_t)b*E_ + e0 + e)*L_ + t0 + c4]);
        tile[e][c4+0] = v.x; tile[e][c4+1] = v.y;
        tile[e][c4+2] = v.z; tile[e][c4+3] = v.w;
    }
    __syncthreads();
    const int st = blockIdx.y;
    #pragma unroll
    for (int it = 0; it < 2; it++) {
        int q = threadIdx.x + it*256;
        int tl = q >> 3, c = q & 7;
        int t = t0 + tl;
        __half hv[8];
        #pragma unroll
        for (int j = 0; j < 8; j++) hv[j] = __float2half(tile[c*8 + j][tl]);
        size_t base = ((size_t)(b*NST + st)*T_PAD + (t & ~7)) * 128;
        uint32_t off = sw128((uint32_t)((t & 7)*128 + c*16));
        *reinterpret_cast<uint4*>(g_xS + base + off) = *reinterpret_cast<const uint4*>(hv);
    }
}

// also zeroes g_s (first 256 blocks), replacing the zero_s launch
__global__ void cvt_w(const float* __restrict__ w) {
    if (blockIdx.x < 256)
        g_s[blockIdx.x*256 + threadIdx.x] = 0.f;
    int i = blockIdx.x * 256 + threadIdx.x;
    if (i >= E_*E_*KS) return;
    int k  = i % KS;
    int r  = i / KS;
    int ic = r % E_, o = r / E_;
    __half h = __float2half(w[i]);
    int ob = o >> 7, m = o & 127, st = ic >> 6, iL = ic & 63;
    size_t atom = ((size_t)((ob*NST + st)*KS + k)*16 + (m >> 3)) * 1024;
    uint32_t off = sw128((uint32_t)((m & 7)*128 + iL*2));
    *reinterpret_cast<__half*>(g_wS + atom + off) = h;
}

// ---------------- main GEMM (conv as 5 shifted GEMMs) + fused score ----------
__global__ void __launch_bounds__(NTHREADS, 1) gemm_conv(
    const float* __restrict__ conv_b, const float* __restrict__ score_w)
{
    extern __shared__ char smem[];
    const uint32_t su = smem_u32(smem);
    const int tid = threadIdx.x, warp = tid >> 5, lane = tid & 31;
    const int b = blockIdx.z, ob = blockIdx.y, t0 = blockIdx.x * BN;
    const int o0 = ob * BM;
    const int wm = (warp >> 2) * 64, wn = (warp & 3) * 64;
    const uint32_t mb0 = su, mb1 = su + 8;       // full barriers, buf 0/1

    if (tid == 0) { MBAR_INIT(mb0, 1); MBAR_INIT(mb1, 1); }
    __syncthreads();

    auto issue = [&](int s) {
        uint32_t mb = (s & 1) ? mb1 : mb0;
        uint32_t dst = su + HDR + (uint32_t)(s & 1)*STAGE;
        MBAR_TX(mb, STAGE);
        bulk_cp(dst, g_wS + (size_t)(ob*NST + s)*A_STG, A_STG, mb);
        bulk_cp(dst + A_STG,
                g_xS + ((size_t)(b*NST + s)*T_PAD + t0)*128, B_STG, mb);
    };
    if (tid == 0) { issue(0); issue(1); }

    float acc[4][8][4];
    #pragma unroll
    for (int mf = 0; mf < 4; mf++)
        #pragma unroll
        for (int nf = 0; nf < 8; nf++)
            #pragma unroll
            for (int q = 0; q < 4; q++) acc[mf][nf][q] = 0.f;

    // per-lane fragment geometry
    const int mA   = wm + (lane & 15);                       // A row (per mf: +16*mf)
    const int mAq  = mA >> 3, mAr = (mA & 7);                // atom row / in-atom row
    const int aKh  = (lane >> 4) * 16;                       // A k-half byte
    const int rB0  = wn + (lane & 7) + ((lane >> 4) & 1)*8;  // B row (per nfp: +16*nfp)
    const int bKh  = ((lane >> 3) & 1) * 16;                 // B k-half byte

    for (int s = 0; s < NST; s++) {
        uint32_t mb = (s & 1) ? mb1 : mb0;
        MBAR_WAIT(mb, (s >> 1) & 1);

        const uint32_t Ab = su + HDR + (uint32_t)(s & 1)*STAGE;
        const uint32_t Bb = Ab + A_STG;

        #pragma unroll
        for (int tap = 0; tap < KS; tap++) {
            const int rt  = rB0 + tap;
            const uint32_t bRow = Bb + (uint32_t)((rt >> 3) * 1024 + (rt & 7) * 128);
            const uint32_t bXor = (uint32_t)((rt & 7) * 16);
            const uint32_t aTap = Ab + (uint32_t)(tap * 16384 + mAq * 1024 + mAr * 128);
            const uint32_t aXor = (uint32_t)(mAr * 16);
            #pragma unroll
            for (int kc = 0; kc < 4; kc++) {
                const uint32_t kbB = (uint32_t)(kc*32 + bKh) ^ bXor;
                const uint32_t kbA = (uint32_t)(kc*32 + aKh) ^ aXor;
                uint32_t bfr[4][4];
                #pragma unroll
                for (int nfp = 0; nfp < 4; nfp++)
                    LDSM4(bfr[nfp][0], bfr[nfp][1], bfr[nfp][2], bfr[nfp][3],
                          bRow + (uint32_t)(nfp * 2048) + kbB);
                uint32_t a[4][4];
                #pragma unroll
                for (int mf = 0; mf < 4; mf++)
                    LDSM4(a[mf][0], a[mf][1], a[mf][2], a[mf][3],
                          aTap + (uint32_t)(mf * 2048) + kbA);
                #pragma unroll
                for (int mf = 0; mf < 4; mf++)
                    #pragma unroll
                    for (int nf = 0; nf < 8; nf++) {
                        int nfp = nf >> 1, q = (nf & 1)*2;
                        mma_f16(acc[mf][nf], a[mf], bfr[nfp][q], bfr[nfp][q+1]);
                    }
            }
        }
        __syncthreads();
        if (tid == 0 && s + 2 < NST) issue(s + 2);
    }

    // ---- epilogue: bias, store y (fp16, padded rows), fused score ----------
    const int ar = lane >> 2, aq = (lane & 3)*2;
    float bvv[4][2], wsv[4][2];
    #pragma unroll
    for (int mf = 0; mf < 4; mf++) {
        int o = o0 + wm + mf*16 + ar;
        bvv[mf][0] = conv_b[o];     bvv[mf][1] = conv_b[o + 8];
        wsv[mf][0] = score_w[o];    wsv[mf][1] = score_w[o + 8];
    }
    #pragma unroll
    for (int mf = 0; mf < 4; mf++) {
        int o = o0 + wm + mf*16 + ar;
        #pragma unroll
        for (int nf = 0; nf < 8; nf++) {
            int t = t0 + wn + nf*8 + aq;
            if (t < LC) {   // t even, LC even => t+1 < LC too
                float y0 = acc[mf][nf][0] + bvv[mf][0];
                float y1 = acc[mf][nf][1] + bvv[mf][0];
                float y2 = acc[mf][nf][2] + bvv[mf][1];
                float y3 = acc[mf][nf][3] + bvv[mf][1];
                size_t r0 = ((size_t)(b*E_ + o))*LCP + t;
                size_t r1 = r0 + (size_t)8*LCP;
                *reinterpret_cast<__half2*>(&g_y[r0]) = __floats2half2_rn(y0, y1);
                *reinterpret_cast<__half2*>(&g_y[r1]) = __floats2half2_rn(y2, y3);
            }
        }
    }
    #pragma unroll
    for (int nf = 0; nf < 8; nf++) {
        float s0 = 0.f, s1 = 0.f;
        #pragma unroll
        for (int mf = 0; mf < 4; mf++) {
            s0 += wsv[mf][0]*(acc[mf][nf][0] + bvv[mf][0])
                + wsv[mf][1]*(acc[mf][nf][2] + bvv[mf][1]);
            s1 += wsv[mf][0]*(acc[mf][nf][1] + bvv[mf][0])
                + wsv[mf][1]*(acc[mf][nf][3] + bvv[mf][1]);
        }
        #pragma unroll
        for (int d = 4; d <= 16; d <<= 1) {
            s0 += __shfl_xor_sync(0xFFFFFFFFu, s0, d);
            s1 += __shfl_xor_sync(0xFFFFFFFFu, s1, d);
        }
        if (lane < 4) {
            int t = t0 + wn + nf*8 + aq;
            if (t < LC)     atomicAdd(&g_s[(size_t)b*L_ + t],     s0);
            if (t + 1 < LC) atomicAdd(&g_s[(size_t)b*L_ + t + 1], s1);
        }
    }
}

// ---------------- GBST combine + downsample (register-window v3) -------------
// Each thread: 8 t (4 outputs), att in registers, 3 vector y-loads per channel.
#define EPT 8
#define ECH 32
__global__ void __launch_bounds__(256) epilogue_kernel(float* __restrict__ out) {
    __shared__ float ss[2056];
    const int tid = threadIdx.x;
    const int b  = blockIdx.y;
    const int T0 = blockIdx.x * 2048;
    const int eg = blockIdx.z * ECH;

    for (int j = tid; j < 2056; j += 256) {
        int t = T0 - 2 + j;
        ss[j] = ((unsigned)t < (unsigned)L_) ? g_s[(size_t)b*L_ + t] : 0.f;
    }
    __syncthreads();

    const int T  = T0 + tid*EPT;
    const int r0 = T % 3;
    float a1[EPT], a2[EPT], a3[EPT];
    #pragma unroll
    for (int j = 0; j < EPT; j++) {
        int tl = tid*EPT + j;
        float sc1 = ss[tl + 2];
        int b2l = tl & ~1;
        float sc2 = 0.5f * (ss[b2l + 2] + ss[b2l + 3]);
        int rj = (r0 + j) % 3;
        int b3l = tl - rj;
        float sc3 = (1.f/3.f) * (ss[b3l + 2] + ss[b3l + 3] + ss[b3l + 4]);
        float m = fmaxf(sc1, fmaxf(sc2, sc3));
        float e1 = __expf(sc1 - m), e2 = __expf(sc2 - m), e3 = __expf(sc3 - m);
        float inv = 1.f / (e1 + e2 + e3);
        a1[j] = e1*inv; a2[j] = e2*inv; a3[j] = e3*inv;
    }

    const bool fast = (T >= 2) && (T + 10 <= LC);
    const int td0 = T >> 1;

    #pragma unroll 2
    for (int ci = 0; ci < ECH; ci++) {
        const __half* yrow = g_y + (size_t)(b*E_ + eg + ci)*LCP;
        float v[12];
        if (fast) {
            __half2 hlo = *reinterpret_cast<const __half2*>(yrow + T - 2);
            v[0] = __low2float(hlo); v[1] = __high2float(hlo);
            uint4 u = *reinterpret_cast<const uint4*>(yrow + T);
            const __half2* hp = reinterpret_cast<const __half2*>(&u);
            #pragma unroll
            for (int q = 0; q < 4; q++) {
                v[2 + 2*q] = __low2float(hp[q]);
                v[3 + 2*q] = __high2float(hp[q]);
            }
            __half2 hhi = *reinterpret_cast<const __half2*>(yrow + T + 8);
            v[10] = __low2float(hhi); v[11] = __high2float(hhi);
        } else {
            #pragma unroll
            for (int i = 0; i < 12; i++) {
                int ti = T - 2 + i;
                v[i] = ((unsigned)ti < (unsigned)LC) ? __half2float(yrow[ti]) : 0.f;
            }
        }
        float p[10];
        #pragma unroll
        for (int i = 0; i < 10; i++) p[i] = v[i] + v[i+1] + v[i+2];
        float z[EPT];
        #pragma unroll
        for (int j = 0; j < EPT; j++) {
            float s2 = 0.5f * (v[(j & ~1) + 2] + v[(j & ~1) + 3]);
            float s3 = (r0 == 0) ? p[j + 2 - ((0 + j) % 3)]
                     : (r0 == 1) ? p[j + 2 - ((1 + j) % 3)]
                                 : p[j + 2 - ((2 + j) % 3)];
            z[j] = a1[j]*v[j+2] + a2[j]*s2 + a3[j]*((1.f/3.f)*s3);
        }
        float4 o;
        o.x = 0.5f*(z[0]+z[1]); o.y = 0.5f*(z[2]+z[3]);
        o.z = 0.5f*(z[4]+z[5]); o.w = 0.5f*(z[6]+z[7]);
        *reinterpret_cast<float4*>(&out[(size_t)(b*E_ + eg + ci)*LD_ + td0]) = o;
    }
}

// ---------------- launch ------------------------------------------------------
extern "C" void kernel_launch(void* const* d_in, const int* in_sizes, int n_in,
                              void* d_out, int out_size) {
    const float* x       = (const float*)d_in[0];
    const float* conv_w  = (const float*)d_in[1];
    const float* conv_b  = (const float*)d_in[2];
    const float* score_w = (const float*)d_in[3];
    float* out = (float*)d_out;

    cvt_x<<<dim3(L_/64, E_/64, B_), 256>>>(x);
    cvt_w<<<(E_*E_*KS + 255)/256, 256>>>(conv_w);

    cudaFuncSetAttribute(gemm_conv, cudaFuncAttributeMaxDynamicSharedMemorySize, SMEM_TOT);
    gemm_conv<<<dim3(L_/BN, E_/BM, B_), NTHREADS, SMEM_TOT>>>(conv_b, score_w);

    epilogue_kernel<<<dim3(L_/2048, B_, E_/ECH), 256>>>(out);
}